// round 8
// baseline (speedup 1.0000x reference)
#include <cuda_runtime.h>
#include <cuda_fp16.h>
#include <cstdint>

#define BATCH 16
#define T 1024
#define D 256
#define BM 128
#define BN 128
#define BK 32
#define NCH (D / BK)    // 8 chunks
#define NSTG 3          // cp.async pipeline stages
#define PADH 40         // halfs per row (32 + 8 pad) = 80 B rows; conflict-free ldmatrix
#define ROWB (PADH * 2) // 80

// Scratch (allocation-free rule: __device__ globals)
__device__ __half g_xs[(size_t)BATCH * T * D];  // fp16(x * w3)
__device__ __half g_yt[(size_t)BATCH * T * D];  // fp16(y)
__device__ float g_bias_x[BATCH * T];
__device__ float g_bias_y[BATCH * T];

__device__ __forceinline__ uint32_t smem_u32(const void* p) {
    uint32_t a;
    asm("{ .reg .u64 t; cvta.to.shared.u64 t, %1; cvt.u32.u64 %0, t; }" : "=r"(a) : "l"(p));
    return a;
}
__device__ __forceinline__ void cp_async16(uint32_t dst, const void* src) {
    asm volatile("cp.async.ca.shared.global [%0], [%1], 16;" :: "r"(dst), "l"(src));
}
#define CP_COMMIT() asm volatile("cp.async.commit_group;" ::: "memory")
#define CP_WAIT(n)  asm volatile("cp.async.wait_group %0;" :: "n"(n) : "memory")

__device__ __forceinline__ void ldsm_x4(uint32_t (&r)[4], uint32_t addr) {
    asm volatile("ldmatrix.sync.aligned.m8n8.x4.shared.b16 {%0,%1,%2,%3}, [%4];"
        : "=r"(r[0]), "=r"(r[1]), "=r"(r[2]), "=r"(r[3]) : "r"(addr));
}

__device__ __forceinline__ void mma_f16(float (&d)[4], const uint32_t (&a)[4],
                                        uint32_t b0, uint32_t b1) {
    asm volatile(
        "mma.sync.aligned.m16n8k16.row.col.f32.f16.f16.f32 "
        "{%0,%1,%2,%3}, {%4,%5,%6,%7}, {%8,%9}, {%0,%1,%2,%3};"
        : "+f"(d[0]), "+f"(d[1]), "+f"(d[2]), "+f"(d[3])
        : "r"(a[0]), "r"(a[1]), "r"(a[2]), "r"(a[3]), "r"(b0), "r"(b1));
}

// ---------------- prep: xs = fp16(x*w3), yt = fp16(y), bias dots in fp32 ----------------
__global__ void __launch_bounds__(256) prep_kernel(
    const float* __restrict__ x, const float* __restrict__ y, const float* __restrict__ WS) {
    int warp = blockIdx.x * 8 + (threadIdx.x >> 5);
    int lane = threadIdx.x & 31;
    const int nrows = BATCH * T;
    if (warp < nrows) {
        const float4* p4 = (const float4*)(x + (size_t)warp * D);
        const float4* w1 = (const float4*)WS;
        const float4* w3 = (const float4*)(WS + 2 * D);
        __half2* xs2 = (__half2*)(g_xs + (size_t)warp * D);
        float s = 0.f;
#pragma unroll
        for (int i = 0; i < 2; i++) {
            int idx = lane + i * 32;
            float4 v = p4[idx], a = w1[idx], c = w3[idx];
            s += v.x * a.x + v.y * a.y + v.z * a.z + v.w * a.w;
            xs2[idx * 2 + 0] = __floats2half2_rn(v.x * c.x, v.y * c.y);
            xs2[idx * 2 + 1] = __floats2half2_rn(v.z * c.z, v.w * c.w);
        }
#pragma unroll
        for (int o = 16; o; o >>= 1) s += __shfl_xor_sync(0xffffffffu, s, o);
        if (lane == 0) g_bias_x[warp] = s;
    } else {
        int row = warp - nrows;
        const float4* p4 = (const float4*)(y + (size_t)row * D);
        const float4* w2 = (const float4*)(WS + D);
        __half2* yt2 = (__half2*)(g_yt + (size_t)row * D);
        float s = 0.f;
#pragma unroll
        for (int i = 0; i < 2; i++) {
            int idx = lane + i * 32;
            float4 v = p4[idx], a = w2[idx];
            s += v.x * a.x + v.y * a.y + v.z * a.z + v.w * a.w;
            yt2[idx * 2 + 0] = __floats2half2_rn(v.x, v.y);
            yt2[idx * 2 + 1] = __floats2half2_rn(v.z, v.w);
        }
#pragma unroll
        for (int o = 16; o; o >>= 1) s += __shfl_xor_sync(0xffffffffu, s, o);
        if (lane == 0) g_bias_y[row] = s;
    }
}

// ---------------- fp16 warp-MMA GEMM: CTA 128x128, 4 warps of 64x64, 3-stage pipe ----------------
#define A_ST (BM * ROWB)              // 10240 B per stage
#define B_ST (BN * ROWB)              // 10240 B per stage
#define SMEM_BYTES (NSTG * (A_ST + B_ST))   // 61440 -> 3 CTAs/SM

__global__ void __launch_bounds__(128, 3) gemm_mma_kernel(float* __restrict__ out) {
    extern __shared__ char smc[];
    const uint32_t sbase = smem_u32(smc);
    const uint32_t bbase0 = sbase + NSTG * A_ST;

    const int tid = threadIdx.x;
    const int wid = tid >> 5, lane = tid & 31;
    const int b = blockIdx.z;
    const int tile_m = blockIdx.y * BM;
    const int tile_n = blockIdx.x * BN;

    const __half* A  = g_xs + ((size_t)b * T + tile_m) * D;
    const __half* Bg = g_yt + ((size_t)b * T + tile_n) * D;

    // Warp layout: 2 (m) x 2 (n); warp tile 64 x 64
    const int warp_m = (wid >> 1) * 64;
    const int warp_n = (wid & 1) * 64;
    const int gid = lane >> 2;
    const int ctg = lane & 3;

    float acc[4][8][4];
#pragma unroll
    for (int i = 0; i < 4; i++)
#pragma unroll
        for (int j = 0; j < 8; j++)
#pragma unroll
            for (int r = 0; r < 4; r++) acc[i][j][r] = 0.f;

    // ldmatrix per-lane offsets (within a stage)
    const uint32_t a_off = (uint32_t)(warp_m + (lane & 15)) * ROWB + (uint32_t)((lane >> 4) * 16);
    const uint32_t b_off = (uint32_t)(warp_n + (lane & 7) + ((lane >> 4) & 1) * 8) * ROWB
                         + (uint32_t)(((lane >> 3) & 1) * 16);

    // cp.async staging: per chunk per operand 128 rows x 4 16B-slots = 512 tasks; 4/thread
    const int st_row = tid >> 2;   // 0..31
    const int st_q   = tid & 3;    // 16B slot (8 halfs)

    auto load_chunk = [&](int chunk, int stg) {
        const __half* ap = A  + chunk * BK + st_q * 8;
        const __half* bp = Bg + chunk * BK + st_q * 8;
        uint32_t adst = sbase  + stg * A_ST + st_row * ROWB + st_q * 16;
        uint32_t bdst = bbase0 + stg * B_ST + st_row * ROWB + st_q * 16;
#pragma unroll
        for (int i = 0; i < 4; i++)
            cp_async16(adst + i * 32 * ROWB, ap + (size_t)(st_row + 32 * i) * D);
#pragma unroll
        for (int i = 0; i < 4; i++)
            cp_async16(bdst + i * 32 * ROWB, bp + (size_t)(st_row + 32 * i) * D);
        CP_COMMIT();
    };

    load_chunk(0, 0);
    load_chunk(1, 1);

    int stg = 0;
#pragma unroll 1
    for (int c = 0; c < NCH; c++) {
        if (c < NCH - 2) CP_WAIT(1); else CP_WAIT(0);
        __syncthreads();
        if (c + 2 < NCH) {
            int ns = stg + 2; if (ns >= NSTG) ns -= NSTG;
            load_chunk(c + 2, ns);
        }

        const uint32_t abase = sbase  + stg * A_ST + a_off;
        const uint32_t bbase = bbase0 + stg * B_ST + b_off;
#pragma unroll
        for (int ks = 0; ks < 2; ks++) {          // 2 k16 steps per 32-chunk
            const uint32_t koff = ks * 32;        // 16 halfs = 32 B
            uint32_t af[4][4], bq[4][4];
#pragma unroll
            for (int mf = 0; mf < 4; mf++)
                ldsm_x4(af[mf], abase + mf * 16 * ROWB + koff);
#pragma unroll
            for (int p = 0; p < 4; p++)
                ldsm_x4(bq[p], bbase + p * 16 * ROWB + koff);
#pragma unroll
            for (int mf = 0; mf < 4; mf++)
#pragma unroll
                for (int nf = 0; nf < 8; nf++)
                    mma_f16(acc[mf][nf], af[mf],
                            bq[nf >> 1][(nf & 1) * 2], bq[nf >> 1][(nf & 1) * 2 + 1]);
        }

        // next stage; compute of chunk c done, its stage becomes free next iteration
        if (++stg == NSTG) stg = 0;
        __syncthreads();
    }

    // Epilogue: + bias_x[row] + bias_y[col], float2 stores
    const float* bxp = g_bias_x + b * T + tile_m + warp_m;
    const float* byp = g_bias_y + b * T + tile_n + warp_n;
    float2 by[8];
#pragma unroll
    for (int nf = 0; nf < 8; nf++)
        by[nf] = *(const float2*)(byp + nf * 8 + ctg * 2);

#pragma unroll
    for (int mf = 0; mf < 4; mf++) {
        int r0 = warp_m + mf * 16 + gid;
        float bx0 = bxp[mf * 16 + gid];
        float bx1 = bxp[mf * 16 + gid + 8];
        float* C0 = out + ((size_t)b * T + tile_m + r0) * T + tile_n + warp_n;
        float* C1 = C0 + 8 * T;
#pragma unroll
        for (int nf = 0; nf < 8; nf++) {
            int coff = nf * 8 + ctg * 2;
            float2 v0 = make_float2(acc[mf][nf][0] + bx0 + by[nf].x,
                                    acc[mf][nf][1] + bx0 + by[nf].y);
            float2 v1 = make_float2(acc[mf][nf][2] + bx1 + by[nf].x,
                                    acc[mf][nf][3] + bx1 + by[nf].y);
            *(float2*)(C0 + coff) = v0;
            *(float2*)(C1 + coff) = v1;
        }
    }
}

extern "C" void kernel_launch(void* const* d_in, const int* in_sizes, int n_in,
                              void* d_out, int out_size) {
    const float* x  = (const float*)d_in[0];
    const float* y  = (const float*)d_in[1];
    const float* WS = (const float*)d_in[2];
    float* out = (float*)d_out;

    cudaFuncSetAttribute(gemm_mma_kernel, cudaFuncAttributeMaxDynamicSharedMemorySize, SMEM_BYTES);

    prep_kernel<<<(2 * BATCH * T) / 8, 256>>>(x, y, WS);

    dim3 grid(T / BN, T / BM, BATCH);   // (8, 8, 16) = 1024 CTAs
    gemm_mma_kernel<<<grid, 128, SMEM_BYTES>>>(out);
}

// round 9
// speedup vs baseline: 1.0484x; 1.0484x over previous
#include <cuda_runtime.h>
#include <cuda_fp16.h>
#include <cstdint>

#define BATCH 16
#define T 1024
#define D 256
#define BM 128
#define BN 128
#define BK 64
#define NCH (D / BK)    // 4 chunks
#define PADH 72         // halfs per row (64 + 8 pad) = 144 B rows; conflict-free ldmatrix
#define ROWB (PADH * 2) // 144

// Scratch (allocation-free rule: __device__ globals)
__device__ __half g_xs[(size_t)BATCH * T * D];  // fp16(x * w3)
__device__ __half g_yt[(size_t)BATCH * T * D];  // fp16(y)
__device__ float g_bias_x[BATCH * T];
__device__ float g_bias_y[BATCH * T];

__device__ __forceinline__ uint32_t smem_u32(const void* p) {
    uint32_t a;
    asm("{ .reg .u64 t; cvta.to.shared.u64 t, %1; cvt.u32.u64 %0, t; }" : "=r"(a) : "l"(p));
    return a;
}
__device__ __forceinline__ void cp_async16(uint32_t dst, const void* src) {
    asm volatile("cp.async.ca.shared.global [%0], [%1], 16;" :: "r"(dst), "l"(src));
}
#define CP_COMMIT() asm volatile("cp.async.commit_group;" ::: "memory")
#define CP_WAIT0()  asm volatile("cp.async.wait_group 0;" ::: "memory")

__device__ __forceinline__ void ldsm_x4(uint32_t (&r)[4], uint32_t addr) {
    asm volatile("ldmatrix.sync.aligned.m8n8.x4.shared.b16 {%0,%1,%2,%3}, [%4];"
        : "=r"(r[0]), "=r"(r[1]), "=r"(r[2]), "=r"(r[3]) : "r"(addr));
}

__device__ __forceinline__ void mma_f16(float (&d)[4], const uint32_t (&a)[4],
                                        uint32_t b0, uint32_t b1) {
    asm volatile(
        "mma.sync.aligned.m16n8k16.row.col.f32.f16.f16.f32 "
        "{%0,%1,%2,%3}, {%4,%5,%6,%7}, {%8,%9}, {%0,%1,%2,%3};"
        : "+f"(d[0]), "+f"(d[1]), "+f"(d[2]), "+f"(d[3])
        : "r"(a[0]), "r"(a[1]), "r"(a[2]), "r"(a[3]), "r"(b0), "r"(b1));
}

// ---------------- prep: xs = fp16(x*w3), yt = fp16(y), bias dots in fp32 ----------------
__global__ void __launch_bounds__(256) prep_kernel(
    const float* __restrict__ x, const float* __restrict__ y, const float* __restrict__ WS) {
    int warp = blockIdx.x * 8 + (threadIdx.x >> 5);
    int lane = threadIdx.x & 31;
    const int nrows = BATCH * T;
    if (warp < nrows) {
        const float4* p4 = (const float4*)(x + (size_t)warp * D);
        const float4* w1 = (const float4*)WS;
        const float4* w3 = (const float4*)(WS + 2 * D);
        __half2* xs2 = (__half2*)(g_xs + (size_t)warp * D);
        float s = 0.f;
#pragma unroll
        for (int i = 0; i < 2; i++) {
            int idx = lane + i * 32;
            float4 v = p4[idx], a = w1[idx], c = w3[idx];
            s += v.x * a.x + v.y * a.y + v.z * a.z + v.w * a.w;
            xs2[idx * 2 + 0] = __floats2half2_rn(v.x * c.x, v.y * c.y);
            xs2[idx * 2 + 1] = __floats2half2_rn(v.z * c.z, v.w * c.w);
        }
#pragma unroll
        for (int o = 16; o; o >>= 1) s += __shfl_xor_sync(0xffffffffu, s, o);
        if (lane == 0) g_bias_x[warp] = s;
    } else {
        int row = warp - nrows;
        const float4* p4 = (const float4*)(y + (size_t)row * D);
        const float4* w2 = (const float4*)(WS + D);
        __half2* yt2 = (__half2*)(g_yt + (size_t)row * D);
        float s = 0.f;
#pragma unroll
        for (int i = 0; i < 2; i++) {
            int idx = lane + i * 32;
            float4 v = p4[idx], a = w2[idx];
            s += v.x * a.x + v.y * a.y + v.z * a.z + v.w * a.w;
            yt2[idx * 2 + 0] = __floats2half2_rn(v.x, v.y);
            yt2[idx * 2 + 1] = __floats2half2_rn(v.z, v.w);
        }
#pragma unroll
        for (int o = 16; o; o >>= 1) s += __shfl_xor_sync(0xffffffffu, s, o);
        if (lane == 0) g_bias_y[row] = s;
    }
}

// ---------------- fp16 warp-MMA GEMM: CTA 128x128, 256 thr, 8 warps of 64x32 ----------------
#define A_BYTES (BM * ROWB)            // 18432
#define B_BYTES (BN * ROWB)            // 18432
#define SMEM_BYTES (2 * A_BYTES + 2 * B_BYTES)   // 73728 -> 2 CTAs/SM (16 warps)

__global__ void __launch_bounds__(256, 2) gemm_mma_kernel(float* __restrict__ out) {
    extern __shared__ char smc[];
    const uint32_t sbase = smem_u32(smc);

    const int tid = threadIdx.x;
    const int wid = tid >> 5, lane = tid & 31;
    const int b = blockIdx.z;
    const int tile_m = blockIdx.y * BM;
    const int tile_n = blockIdx.x * BN;

    const __half* A  = g_xs + ((size_t)b * T + tile_m) * D;
    const __half* Bg = g_yt + ((size_t)b * T + tile_n) * D;

    // Warp layout: 2 (m) x 4 (n); warp tile 64 x 32
    const int warp_m = (wid >> 2) * 64;
    const int warp_n = (wid & 3) * 32;
    const int gid = lane >> 2;
    const int ctg = lane & 3;

    float acc[4][4][4];
#pragma unroll
    for (int i = 0; i < 4; i++)
#pragma unroll
        for (int j = 0; j < 4; j++)
#pragma unroll
            for (int r = 0; r < 4; r++) acc[i][j][r] = 0.f;

    // ldmatrix per-lane base addresses (within a stage)
    const uint32_t a_off = (uint32_t)(warp_m + (lane & 15)) * ROWB + (uint32_t)((lane >> 4) * 16);
    const uint32_t b_off = (uint32_t)(warp_n + (lane & 7) + ((lane >> 4) & 1) * 8) * ROWB
                         + (uint32_t)(((lane >> 3) & 1) * 16);

    // cp.async staging: per chunk per operand 128 rows x 8 16B-slots = 1024 tasks; 4/thread
    const int st_row = tid >> 3;   // 0..31
    const int st_q   = tid & 7;    // 16B slot (8 halfs)

    auto load_chunk = [&](int chunk, int buf) {
        const __half* ap = A  + chunk * BK + st_q * 8;
        const __half* bp = Bg + chunk * BK + st_q * 8;
        uint32_t adst = sbase + buf * A_BYTES + st_row * ROWB + st_q * 16;
        uint32_t bdst = sbase + 2 * A_BYTES + buf * B_BYTES + st_row * ROWB + st_q * 16;
#pragma unroll
        for (int i = 0; i < 4; i++)
            cp_async16(adst + i * 32 * ROWB, ap + (size_t)(st_row + 32 * i) * D);
#pragma unroll
        for (int i = 0; i < 4; i++)
            cp_async16(bdst + i * 32 * ROWB, bp + (size_t)(st_row + 32 * i) * D);
    };

    load_chunk(0, 0);
    CP_COMMIT();
    CP_WAIT0();
    __syncthreads();

#pragma unroll 1
    for (int c = 0; c < NCH; c++) {
        if (c + 1 < NCH) {
            load_chunk(c + 1, (c + 1) & 1);
            CP_COMMIT();
        }

        const uint32_t abase = sbase + (c & 1) * A_BYTES + a_off;
        const uint32_t bbase = sbase + 2 * A_BYTES + (c & 1) * B_BYTES + b_off;
#pragma unroll
        for (int ks = 0; ks < 4; ks++) {          // 4 k16 steps per 64-chunk
            const uint32_t koff = ks * 32;        // 16 halfs = 32 B
            uint32_t af[4][4], bq[2][4];
#pragma unroll
            for (int mf = 0; mf < 4; mf++)
                ldsm_x4(af[mf], abase + mf * 16 * ROWB + koff);
#pragma unroll
            for (int p = 0; p < 2; p++)
                ldsm_x4(bq[p], bbase + p * 16 * ROWB + koff);
#pragma unroll
            for (int mf = 0; mf < 4; mf++)
#pragma unroll
                for (int nf = 0; nf < 4; nf++)
                    mma_f16(acc[mf][nf], af[mf],
                            bq[nf >> 1][(nf & 1) * 2], bq[nf >> 1][(nf & 1) * 2 + 1]);
        }

        if (c + 1 < NCH) {
            CP_WAIT0();
            __syncthreads();
        }
    }

    // Epilogue: + bias_x[row] + bias_y[col], float2 stores
    const float* bxp = g_bias_x + b * T + tile_m + warp_m;
    const float* byp = g_bias_y + b * T + tile_n + warp_n;
    float2 by[4];
#pragma unroll
    for (int nf = 0; nf < 4; nf++)
        by[nf] = *(const float2*)(byp + nf * 8 + ctg * 2);

#pragma unroll
    for (int mf = 0; mf < 4; mf++) {
        int r0 = warp_m + mf * 16 + gid;
        float bx0 = bxp[mf * 16 + gid];
        float bx1 = bxp[mf * 16 + gid + 8];
        float* C0 = out + ((size_t)b * T + tile_m + r0) * T + tile_n + warp_n;
        float* C1 = C0 + 8 * T;
#pragma unroll
        for (int nf = 0; nf < 4; nf++) {
            int coff = nf * 8 + ctg * 2;
            float2 v0 = make_float2(acc[mf][nf][0] + bx0 + by[nf].x,
                                    acc[mf][nf][1] + bx0 + by[nf].y);
            float2 v1 = make_float2(acc[mf][nf][2] + bx1 + by[nf].x,
                                    acc[mf][nf][3] + bx1 + by[nf].y);
            *(float2*)(C0 + coff) = v0;
            *(float2*)(C1 + coff) = v1;
        }
    }
}

extern "C" void kernel_launch(void* const* d_in, const int* in_sizes, int n_in,
                              void* d_out, int out_size) {
    const float* x  = (const float*)d_in[0];
    const float* y  = (const float*)d_in[1];
    const float* WS = (const float*)d_in[2];
    float* out = (float*)d_out;

    cudaFuncSetAttribute(gemm_mma_kernel, cudaFuncAttributeMaxDynamicSharedMemorySize, SMEM_BYTES);

    prep_kernel<<<(2 * BATCH * T) / 8, 256>>>(x, y, WS);

    dim3 grid(T / BN, T / BM, BATCH);   // (8, 8, 16) = 1024 CTAs
    gemm_mma_kernel<<<grid, 256, SMEM_BYTES>>>(out);
}

// round 10
// speedup vs baseline: 1.2039x; 1.1483x over previous
#include <cuda_runtime.h>
#include <cuda.h>
#include <cuda_fp16.h>
#include <cstdint>

#define BATCH 16
#define T 1024
#define D 256
#define BM 128
#define BN 128
#define BK 64
#define NCH (D / BK)    // 4 chunks
#define NSTG 3

// Scratch (allocation-free rule: __device__ globals). 1KB-aligned for TMA.
__device__ __align__(1024) __half g_xs[(size_t)BATCH * T * D];  // fp16(x * w3)
__device__ __align__(1024) __half g_yt[(size_t)BATCH * T * D];  // fp16(y)
__device__ float g_bias_x[BATCH * T];
__device__ float g_bias_y[BATCH * T];

__device__ __forceinline__ uint32_t smem_u32(const void* p) {
    uint32_t a;
    asm("{ .reg .u64 t; cvta.to.shared.u64 t, %1; cvt.u32.u64 %0, t; }" : "=r"(a) : "l"(p));
    return a;
}
__device__ __forceinline__ void ldsm_x4(uint32_t (&r)[4], uint32_t addr) {
    asm volatile("ldmatrix.sync.aligned.m8n8.x4.shared.b16 {%0,%1,%2,%3}, [%4];"
        : "=r"(r[0]), "=r"(r[1]), "=r"(r[2]), "=r"(r[3]) : "r"(addr));
}
__device__ __forceinline__ void mma_f16(float (&d)[4], const uint32_t (&a)[4],
                                        uint32_t b0, uint32_t b1) {
    asm volatile(
        "mma.sync.aligned.m16n8k16.row.col.f32.f16.f16.f32 "
        "{%0,%1,%2,%3}, {%4,%5,%6,%7}, {%8,%9}, {%0,%1,%2,%3};"
        : "+f"(d[0]), "+f"(d[1]), "+f"(d[2]), "+f"(d[3])
        : "r"(a[0]), "r"(a[1]), "r"(a[2]), "r"(a[3]), "r"(b0), "r"(b1));
}
#define MBARRIER_INIT(mbar, cnt) \
    asm volatile("mbarrier.init.shared.b64 [%0], %1;" :: "r"((uint32_t)(mbar)), "r"((uint32_t)(cnt)) : "memory")
#define MBARRIER_EXPECT_TX(mbar, bytes) \
    asm volatile("mbarrier.arrive.expect_tx.shared.b64 _, [%0], %1;" \
        :: "r"((uint32_t)(mbar)), "r"((uint32_t)(bytes)) : "memory")
#define MBARRIER_WAIT_PARITY(mbar, parity) do { \
    uint32_t _m = (uint32_t)(mbar), _p = (uint32_t)(parity), _d; \
    asm volatile("{ .reg .pred p; mbarrier.try_wait.parity.acquire.cta.shared::cta.b64 p, [%1], %2;" \
                 " selp.b32 %0,1,0,p; }" : "=r"(_d) : "r"(_m), "r"(_p) : "memory"); \
    if (!_d) { \
        asm volatile("{ .reg .pred P1; WL_%=:" \
            " mbarrier.try_wait.parity.acquire.cta.shared::cta.b64 P1, [%0], %1, 0x989680;" \
            " @P1 bra.uni WD_%=; bra.uni WL_%=; WD_%=: }" :: "r"(_m), "r"(_p) : "memory"); \
    } \
} while (0)
__device__ __forceinline__ void tma_load_2d(uint32_t dst, const void* map,
                                            int x, int y, uint32_t mbar) {
    asm volatile(
        "cp.async.bulk.tensor.2d.shared::cta.global.tile.mbarrier::complete_tx::bytes "
        "[%0], [%1, {%2, %3}], [%4];"
        :: "r"(dst), "l"(map), "r"(x), "r"(y), "r"(mbar) : "memory");
}
// legacy cp.async (fallback path)
__device__ __forceinline__ void cp_async16(uint32_t dst, const void* src) {
    asm volatile("cp.async.ca.shared.global [%0], [%1], 16;" :: "r"(dst), "l"(src));
}
#define CP_COMMIT() asm volatile("cp.async.commit_group;" ::: "memory")
#define CP_WAIT0()  asm volatile("cp.async.wait_group 0;" ::: "memory")

// ---------------- prep: xs = fp16(x*w3), yt = fp16(y), bias dots in fp32 ----------------
__global__ void __launch_bounds__(256) prep_kernel(
    const float* __restrict__ x, const float* __restrict__ y, const float* __restrict__ WS) {
    int warp = blockIdx.x * 8 + (threadIdx.x >> 5);
    int lane = threadIdx.x & 31;
    const int nrows = BATCH * T;
    if (warp < nrows) {
        const float4* p4 = (const float4*)(x + (size_t)warp * D);
        const float4* w1 = (const float4*)WS;
        const float4* w3 = (const float4*)(WS + 2 * D);
        __half2* xs2 = (__half2*)(g_xs + (size_t)warp * D);
        float s = 0.f;
#pragma unroll
        for (int i = 0; i < 2; i++) {
            int idx = lane + i * 32;
            float4 v = p4[idx], a = w1[idx], c = w3[idx];
            s += v.x * a.x + v.y * a.y + v.z * a.z + v.w * a.w;
            xs2[idx * 2 + 0] = __floats2half2_rn(v.x * c.x, v.y * c.y);
            xs2[idx * 2 + 1] = __floats2half2_rn(v.z * c.z, v.w * c.w);
        }
#pragma unroll
        for (int o = 16; o; o >>= 1) s += __shfl_xor_sync(0xffffffffu, s, o);
        if (lane == 0) g_bias_x[warp] = s;
    } else {
        int row = warp - nrows;
        const float4* p4 = (const float4*)(y + (size_t)row * D);
        const float4* w2 = (const float4*)(WS + D);
        __half2* yt2 = (__half2*)(g_yt + (size_t)row * D);
        float s = 0.f;
#pragma unroll
        for (int i = 0; i < 2; i++) {
            int idx = lane + i * 32;
            float4 v = p4[idx], a = w2[idx];
            s += v.x * a.x + v.y * a.y + v.z * a.z + v.w * a.w;
            yt2[idx * 2 + 0] = __floats2half2_rn(v.x, v.y);
            yt2[idx * 2 + 1] = __floats2half2_rn(v.z, v.w);
        }
#pragma unroll
        for (int o = 16; o; o >>= 1) s += __shfl_xor_sync(0xffffffffu, s, o);
        if (lane == 0) g_bias_y[row] = s;
    }
}

// ---------------- TMA + mbarrier fp16 MMA GEMM ----------------
// Stage: A tile 128x64 halfs (16KB, SW128) + B tile same. 3 stages + mbarriers.
#define ST_BYTES 32768
#define A_TILE 16384
#define OFF_MBAR (NSTG * ST_BYTES)          // 98304
#define SMEM_TMA (OFF_MBAR + 64)

__global__ void __launch_bounds__(256, 2) gemm_tma_kernel(
    float* __restrict__ out,
    const __grid_constant__ CUtensorMap mA,
    const __grid_constant__ CUtensorMap mB) {
    extern __shared__ char smc[];
    const uint32_t sbase = smem_u32(smc);

    const int tid = threadIdx.x;
    const int wid = tid >> 5, lane = tid & 31;
    const int b = blockIdx.z;
    const int tile_m = blockIdx.y * BM;
    const int tile_n = blockIdx.x * BN;
    const int rowA0 = b * T + tile_m;
    const int rowB0 = b * T + tile_n;

    // Warp layout: 2 (m) x 4 (n); warp tile 64 x 32
    const int warp_m = (wid >> 2) * 64;
    const int warp_n = (wid & 3) * 32;
    const int gid = lane >> 2;
    const int ctg = lane & 3;

    if (tid == 0) {
#pragma unroll
        for (int s = 0; s < NSTG; s++) MBARRIER_INIT(sbase + OFF_MBAR + s * 8, 1);
    }
    __syncthreads();

    auto issue = [&](int chunk) {
        int stg = chunk % NSTG;
        uint32_t mb = sbase + OFF_MBAR + stg * 8;
        MBARRIER_EXPECT_TX(mb, ST_BYTES);
        tma_load_2d(sbase + stg * ST_BYTES,          &mA, chunk * BK, rowA0, mb);
        tma_load_2d(sbase + stg * ST_BYTES + A_TILE, &mB, chunk * BK, rowB0, mb);
    };
    if (tid == 0) { issue(0); issue(1); }

    float acc[4][4][4];
#pragma unroll
    for (int i = 0; i < 4; i++)
#pragma unroll
        for (int j = 0; j < 4; j++)
#pragma unroll
            for (int r = 0; r < 4; r++) acc[i][j][r] = 0.f;

    // ldmatrix lane addressing within SW128-swizzled 128x64h tile (128B rows):
    // addr(row, unit16B) = row*128 + ((unit*16) ^ ((row&7)*16))
    const int rA = warp_m + (lane & 15);             // (rA & 7) invariant under +16*mf
    const uint32_t swzA = (uint32_t)(rA & 7) * 16;
    const uint32_t aoff0 = (uint32_t)rA * 128;
    const uint32_t aub = (uint32_t)(lane >> 4);      // k 16B-unit base (0/1)
    const int rB = warp_n + (lane & 7) + ((lane >> 4) & 1) * 8;
    const uint32_t swzB = (uint32_t)(rB & 7) * 16;
    const uint32_t boff0 = (uint32_t)rB * 128;
    const uint32_t bub = (uint32_t)((lane >> 3) & 1);

#pragma unroll 1
    for (int c = 0; c < NCH; c++) {
        const int stg = c % NSTG;
        MBARRIER_WAIT_PARITY(sbase + OFF_MBAR + stg * 8, (c / NSTG) & 1);
        if (tid == 0 && c + 2 < NCH) issue(c + 2);

        const uint32_t abase = sbase + stg * ST_BYTES + aoff0;
        const uint32_t bbase = sbase + stg * ST_BYTES + A_TILE + boff0;
#pragma unroll
        for (int ks = 0; ks < 4; ks++) {
            uint32_t af[4][4], bq[2][4];
            const uint32_t aku = ((aub + ks * 2) * 16) ^ swzA;
            const uint32_t bku = ((bub + ks * 2) * 16) ^ swzB;
#pragma unroll
            for (int mf = 0; mf < 4; mf++)
                ldsm_x4(af[mf], abase + (uint32_t)mf * (16 * 128) + aku);
#pragma unroll
            for (int p = 0; p < 2; p++)
                ldsm_x4(bq[p], bbase + (uint32_t)p * (16 * 128) + bku);
#pragma unroll
            for (int mf = 0; mf < 4; mf++)
#pragma unroll
                for (int nf = 0; nf < 4; nf++)
                    mma_f16(acc[mf][nf], af[mf],
                            bq[nf >> 1][(nf & 1) * 2], bq[nf >> 1][(nf & 1) * 2 + 1]);
        }
        if (c + 1 < NCH) __syncthreads();   // stage reuse safety
    }

    // Epilogue: + bias_x[row] + bias_y[col], float2 stores
    const float* bxp = g_bias_x + b * T + tile_m + warp_m;
    const float* byp = g_bias_y + b * T + tile_n + warp_n;
    float2 by[4];
#pragma unroll
    for (int nf = 0; nf < 4; nf++)
        by[nf] = *(const float2*)(byp + nf * 8 + ctg * 2);

#pragma unroll
    for (int mf = 0; mf < 4; mf++) {
        int r0 = warp_m + mf * 16 + gid;
        float bx0 = bxp[mf * 16 + gid];
        float bx1 = bxp[mf * 16 + gid + 8];
        float* C0 = out + ((size_t)b * T + tile_m + r0) * T + tile_n + warp_n;
        float* C1 = C0 + 8 * T;
#pragma unroll
        for (int nf = 0; nf < 4; nf++) {
            int coff = nf * 8 + ctg * 2;
            float2 v0 = make_float2(acc[mf][nf][0] + bx0 + by[nf].x,
                                    acc[mf][nf][1] + bx0 + by[nf].y);
            float2 v1 = make_float2(acc[mf][nf][2] + bx1 + by[nf].x,
                                    acc[mf][nf][3] + bx1 + by[nf].y);
            *(float2*)(C0 + coff) = v0;
            *(float2*)(C1 + coff) = v1;
        }
    }
}

// ---------------- fallback: R9 cp.async kernel (if driver entry point unavailable) ----------------
#define PADH 72
#define ROWB (PADH * 2)
#define A_BYTES (BM * ROWB)
#define B_BYTES (BN * ROWB)
#define SMEM_CP (2 * A_BYTES + 2 * B_BYTES)

__global__ void __launch_bounds__(256, 2) gemm_cp_kernel(float* __restrict__ out) {
    extern __shared__ char smc[];
    const uint32_t sbase = smem_u32(smc);
    const int tid = threadIdx.x;
    const int wid = tid >> 5, lane = tid & 31;
    const int b = blockIdx.z;
    const int tile_m = blockIdx.y * BM;
    const int tile_n = blockIdx.x * BN;
    const __half* A  = g_xs + ((size_t)b * T + tile_m) * D;
    const __half* Bg = g_yt + ((size_t)b * T + tile_n) * D;
    const int warp_m = (wid >> 2) * 64;
    const int warp_n = (wid & 3) * 32;
    const int gid = lane >> 2, ctg = lane & 3;

    float acc[4][4][4];
#pragma unroll
    for (int i = 0; i < 4; i++)
#pragma unroll
        for (int j = 0; j < 4; j++)
#pragma unroll
            for (int r = 0; r < 4; r++) acc[i][j][r] = 0.f;

    const uint32_t a_off = (uint32_t)(warp_m + (lane & 15)) * ROWB + (uint32_t)((lane >> 4) * 16);
    const uint32_t b_off = (uint32_t)(warp_n + (lane & 7) + ((lane >> 4) & 1) * 8) * ROWB
                         + (uint32_t)(((lane >> 3) & 1) * 16);
    const int st_row = tid >> 3, st_q = tid & 7;

    auto load_chunk = [&](int chunk, int buf) {
        const __half* ap = A  + chunk * BK + st_q * 8;
        const __half* bp = Bg + chunk * BK + st_q * 8;
        uint32_t adst = sbase + buf * A_BYTES + st_row * ROWB + st_q * 16;
        uint32_t bdst = sbase + 2 * A_BYTES + buf * B_BYTES + st_row * ROWB + st_q * 16;
#pragma unroll
        for (int i = 0; i < 4; i++)
            cp_async16(adst + i * 32 * ROWB, ap + (size_t)(st_row + 32 * i) * D);
#pragma unroll
        for (int i = 0; i < 4; i++)
            cp_async16(bdst + i * 32 * ROWB, bp + (size_t)(st_row + 32 * i) * D);
    };

    load_chunk(0, 0);
    CP_COMMIT();
    CP_WAIT0();
    __syncthreads();

#pragma unroll 1
    for (int c = 0; c < NCH; c++) {
        if (c + 1 < NCH) { load_chunk(c + 1, (c + 1) & 1); CP_COMMIT(); }
        const uint32_t abase = sbase + (c & 1) * A_BYTES + a_off;
        const uint32_t bbase = sbase + 2 * A_BYTES + (c & 1) * B_BYTES + b_off;
#pragma unroll
        for (int ks = 0; ks < 4; ks++) {
            const uint32_t koff = ks * 32;
            uint32_t af[4][4], bq[2][4];
#pragma unroll
            for (int mf = 0; mf < 4; mf++)
                ldsm_x4(af[mf], abase + mf * 16 * ROWB + koff);
#pragma unroll
            for (int p = 0; p < 2; p++)
                ldsm_x4(bq[p], bbase + p * 16 * ROWB + koff);
#pragma unroll
            for (int mf = 0; mf < 4; mf++)
#pragma unroll
                for (int nf = 0; nf < 4; nf++)
                    mma_f16(acc[mf][nf], af[mf],
                            bq[nf >> 1][(nf & 1) * 2], bq[nf >> 1][(nf & 1) * 2 + 1]);
        }
        if (c + 1 < NCH) { CP_WAIT0(); __syncthreads(); }
    }

    const float* bxp = g_bias_x + b * T + tile_m + warp_m;
    const float* byp = g_bias_y + b * T + tile_n + warp_n;
    float2 by[4];
#pragma unroll
    for (int nf = 0; nf < 4; nf++)
        by[nf] = *(const float2*)(byp + nf * 8 + ctg * 2);
#pragma unroll
    for (int mf = 0; mf < 4; mf++) {
        int r0 = warp_m + mf * 16 + gid;
        float bx0 = bxp[mf * 16 + gid];
        float bx1 = bxp[mf * 16 + gid + 8];
        float* C0 = out + ((size_t)b * T + tile_m + r0) * T + tile_n + warp_n;
        float* C1 = C0 + 8 * T;
#pragma unroll
        for (int nf = 0; nf < 4; nf++) {
            int coff = nf * 8 + ctg * 2;
            float2 v0 = make_float2(acc[mf][nf][0] + bx0 + by[nf].x,
                                    acc[mf][nf][1] + bx0 + by[nf].y);
            float2 v1 = make_float2(acc[mf][nf][2] + bx1 + by[nf].x,
                                    acc[mf][nf][3] + bx1 + by[nf].y);
            *(float2*)(C0 + coff) = v0;
            *(float2*)(C1 + coff) = v1;
        }
    }
}

typedef CUresult (*PFN_encodeTiled)(
    CUtensorMap*, CUtensorMapDataType, cuuint32_t, void*,
    const cuuint64_t*, const cuuint64_t*, const cuuint32_t*, const cuuint32_t*,
    CUtensorMapInterleave, CUtensorMapSwizzle, CUtensorMapL2promotion,
    CUtensorMapFloatOOBfill);

extern "C" void kernel_launch(void* const* d_in, const int* in_sizes, int n_in,
                              void* d_out, int out_size) {
    const float* x  = (const float*)d_in[0];
    const float* y  = (const float*)d_in[1];
    const float* WS = (const float*)d_in[2];
    float* out = (float*)d_out;

    prep_kernel<<<(2 * BATCH * T) / 8, 256>>>(x, y, WS);

    // Try TMA path
    void* fn = nullptr;
    cudaDriverEntryPointQueryResult qr = cudaDriverEntryPointSymbolNotFound;
    cudaGetDriverEntryPoint("cuTensorMapEncodeTiled", &fn, cudaEnableDefault, &qr);

    bool tma_ok = (fn != nullptr && qr == cudaDriverEntryPointSuccess);
    CUtensorMap mA, mB;
    if (tma_ok) {
        void *xs_ptr = nullptr, *yt_ptr = nullptr;
        cudaGetSymbolAddress(&xs_ptr, g_xs);
        cudaGetSymbolAddress(&yt_ptr, g_yt);
        cuuint64_t dims[2]    = {(cuuint64_t)D, (cuuint64_t)(BATCH * T)};
        cuuint64_t strides[1] = {(cuuint64_t)(D * 2)};
        cuuint32_t box[2]     = {BK, BM};
        cuuint32_t estr[2]    = {1, 1};
        PFN_encodeTiled enc = (PFN_encodeTiled)fn;
        CUresult r1 = enc(&mA, CU_TENSOR_MAP_DATA_TYPE_UINT16, 2, xs_ptr, dims, strides,
                          box, estr, CU_TENSOR_MAP_INTERLEAVE_NONE,
                          CU_TENSOR_MAP_SWIZZLE_128B, CU_TENSOR_MAP_L2_PROMOTION_L2_128B,
                          CU_TENSOR_MAP_FLOAT_OOB_FILL_NONE);
        CUresult r2 = enc(&mB, CU_TENSOR_MAP_DATA_TYPE_UINT16, 2, yt_ptr, dims, strides,
                          box, estr, CU_TENSOR_MAP_INTERLEAVE_NONE,
                          CU_TENSOR_MAP_SWIZZLE_128B, CU_TENSOR_MAP_L2_PROMOTION_L2_128B,
                          CU_TENSOR_MAP_FLOAT_OOB_FILL_NONE);
        tma_ok = (r1 == CUDA_SUCCESS && r2 == CUDA_SUCCESS);
    }

    dim3 grid(T / BN, T / BM, BATCH);   // (8, 8, 16) = 1024 CTAs
    if (tma_ok) {
        cudaFuncSetAttribute(gemm_tma_kernel, cudaFuncAttributeMaxDynamicSharedMemorySize, SMEM_TMA);
        gemm_tma_kernel<<<grid, 256, SMEM_TMA>>>(out, mA, mB);
    } else {
        cudaFuncSetAttribute(gemm_cp_kernel, cudaFuncAttributeMaxDynamicSharedMemorySize, SMEM_CP);
        gemm_cp_kernel<<<grid, 256, SMEM_CP>>>(out);
    }
}